// round 1
// baseline (speedup 1.0000x reference)
#include <cuda_runtime.h>
#include <cuda_bf16.h>
#include <math_constants.h>

// Problem constants
#define D     256          // embedding dim (K of both GEMMs)
#define BM    128
#define BN    128
#define BK    16
#define TM    8
#define TN    8
#define NTHREADS 256

// Scratch (device globals; no cudaMalloc allowed)
__device__ float g_cn[8192];       // codebook row norms
__device__ int   g_idx[32768];     // argmin index per row
__device__ float g_part[512];      // per-block loss partial sums

// ---------------------------------------------------------------------------
// Kernel 1: codebook norms  cn[k] = sum_d e[k][d]^2
// ---------------------------------------------------------------------------
__global__ void cnorm_kernel(const float* __restrict__ cb, int Kcodes) {
    int k = blockIdx.x * blockDim.x + threadIdx.x;
    if (k >= Kcodes) return;
    const float4* row = reinterpret_cast<const float4*>(cb + (size_t)k * D);
    float s = 0.f;
#pragma unroll 8
    for (int i = 0; i < D / 4; ++i) {
        float4 v = row[i];
        s += v.x * v.x + v.y * v.y + v.z * v.z + v.w * v.w;
    }
    g_cn[k] = s;
}

// ---------------------------------------------------------------------------
// Shared tile loader: loads a [128 rows x 16 k] tile, stored k-major in smem.
// src rows have leading dimension D (=256). 256 threads, 2 float4 each.
// ---------------------------------------------------------------------------
__device__ __forceinline__ void load_tile(float dst[BK][BM + 4],
                                          const float* __restrict__ src,
                                          int rowBase, int kt, int tid) {
#pragma unroll
    for (int p = 0; p < 2; ++p) {
        int id = tid + p * NTHREADS;      // 0..511
        int r  = id >> 2;                 // 0..127
        int c4 = id & 3;                  // 0..3
        float4 v = *reinterpret_cast<const float4*>(
            src + (size_t)(rowBase + r) * D + kt * BK + c4 * 4);
        dst[c4 * 4 + 0][r] = v.x;
        dst[c4 * 4 + 1][r] = v.y;
        dst[c4 * 4 + 2][r] = v.z;
        dst[c4 * 4 + 3][r] = v.w;
    }
}

// ---------------------------------------------------------------------------
// Kernel 2: projection  z = x @ W^T + b   (M x 256, K = 256)
// grid: (M/128, 256/128), block 256 threads (16x16), 8x8 register tile
// ---------------------------------------------------------------------------
__global__ __launch_bounds__(NTHREADS, 2)
void proj_kernel(const float* __restrict__ x, const float* __restrict__ W,
                 const float* __restrict__ b, float* __restrict__ z) {
    __shared__ float Xs[BK][BM + 4];
    __shared__ float Ws[BK][BN + 4];

    int tid = threadIdx.x;
    int tx = tid & 15, ty = tid >> 4;
    int rowBase = blockIdx.x * BM;
    int colBase = blockIdx.y * BN;

    float acc[TM][TN];
#pragma unroll
    for (int i = 0; i < TM; ++i)
#pragma unroll
        for (int j = 0; j < TN; ++j) acc[i][j] = 0.f;

    for (int kt = 0; kt < D / BK; ++kt) {
        load_tile(Xs, x, rowBase, kt, tid);
        load_tile(Ws, W, colBase, kt, tid);
        __syncthreads();
#pragma unroll
        for (int kk = 0; kk < BK; ++kk) {
            float a[TM], bb[TN];
#pragma unroll
            for (int i = 0; i < TM; ++i) a[i] = Xs[kk][ty * TM + i];
#pragma unroll
            for (int j = 0; j < TN; ++j) bb[j] = Ws[kk][tx * TN + j];
#pragma unroll
            for (int i = 0; i < TM; ++i)
#pragma unroll
                for (int j = 0; j < TN; ++j)
                    acc[i][j] = fmaf(a[i], bb[j], acc[i][j]);
        }
        __syncthreads();
    }

    // epilogue: add bias, write z
    int col0 = colBase + tx * TN;
#pragma unroll
    for (int i = 0; i < TM; ++i) {
        int row = rowBase + ty * TM + i;
        float* zrow = z + (size_t)row * D + col0;
#pragma unroll
        for (int j4 = 0; j4 < TN / 4; ++j4) {
            float4 v;
            v.x = acc[i][j4 * 4 + 0] + b[col0 + j4 * 4 + 0];
            v.y = acc[i][j4 * 4 + 1] + b[col0 + j4 * 4 + 1];
            v.z = acc[i][j4 * 4 + 2] + b[col0 + j4 * 4 + 2];
            v.w = acc[i][j4 * 4 + 3] + b[col0 + j4 * 4 + 3];
            *reinterpret_cast<float4*>(zrow + j4 * 4) = v;
        }
    }
}

// ---------------------------------------------------------------------------
// Kernel 3: distance argmin.
// For each row n: idx[n] = argmin_k ( cn[k] - 2 * z[n].e[k] )   (||z||^2 const)
// Each block owns 128 rows and sweeps all Kcodes in tiles of 128.
// ---------------------------------------------------------------------------
__global__ __launch_bounds__(NTHREADS, 2)
void dist_argmin_kernel(const float* __restrict__ z, const float* __restrict__ cb,
                        int Kcodes) {
    __shared__ float Zs[BK][BM + 4];
    __shared__ float Es[BK][BN + 4];
    __shared__ float rv[BM][16];
    __shared__ int   ri[BM][16];

    int tid = threadIdx.x;
    int tx = tid & 15, ty = tid >> 4;
    int rowBase = blockIdx.x * BM;

    float bestv[TM];
    int   besti[TM];
#pragma unroll
    for (int i = 0; i < TM; ++i) { bestv[i] = CUDART_INF_F; besti[i] = 0; }

    for (int nt = 0; nt < Kcodes / BN; ++nt) {
        float acc[TM][TN];
#pragma unroll
        for (int i = 0; i < TM; ++i)
#pragma unroll
            for (int j = 0; j < TN; ++j) acc[i][j] = 0.f;

        int codeBase = nt * BN;
        for (int kt = 0; kt < D / BK; ++kt) {
            load_tile(Zs, z, rowBase, kt, tid);
            load_tile(Es, cb, codeBase, kt, tid);
            __syncthreads();
#pragma unroll
            for (int kk = 0; kk < BK; ++kk) {
                float a[TM], bb[TN];
#pragma unroll
                for (int i = 0; i < TM; ++i) a[i] = Zs[kk][ty * TM + i];
#pragma unroll
                for (int j = 0; j < TN; ++j) bb[j] = Es[kk][tx * TN + j];
#pragma unroll
                for (int i = 0; i < TM; ++i)
#pragma unroll
                    for (int j = 0; j < TN; ++j)
                        acc[i][j] = fmaf(a[i], bb[j], acc[i][j]);
            }
            __syncthreads();
        }

        // distance eval + running argmin (ascending code order -> first-min)
        float cns[TN];
#pragma unroll
        for (int j = 0; j < TN; ++j) cns[j] = g_cn[codeBase + tx * TN + j];
#pragma unroll
        for (int i = 0; i < TM; ++i) {
#pragma unroll
            for (int j = 0; j < TN; ++j) {
                float d = fmaf(-2.f, acc[i][j], cns[j]);
                int code = codeBase + tx * TN + j;
                if (d < bestv[i]) { bestv[i] = d; besti[i] = code; }
            }
        }
    }

    // cross-thread (tx) reduction per row, ascending tx keeps lowest index
#pragma unroll
    for (int i = 0; i < TM; ++i) {
        rv[ty * TM + i][tx] = bestv[i];
        ri[ty * TM + i][tx] = besti[i];
    }
    __syncthreads();
    if (tid < BM) {
        float bv = rv[tid][0];
        int   bi = ri[tid][0];
#pragma unroll
        for (int t = 1; t < 16; ++t) {
            if (rv[tid][t] < bv) { bv = rv[tid][t]; bi = ri[tid][t]; }
        }
        g_idx[rowBase + tid] = bi;
    }
}

// ---------------------------------------------------------------------------
// Kernel 4: gather q, write x_recon = z + (q - z) in-place, loss partials
// ---------------------------------------------------------------------------
__global__ void gather_loss_kernel(float* __restrict__ out,
                                   const float* __restrict__ cb,
                                   int total4) {
    int t = blockIdx.x * blockDim.x + threadIdx.x;
    int stride = gridDim.x * blockDim.x;
    float s = 0.f;
    for (int e4 = t; e4 < total4; e4 += stride) {
        int n  = e4 >> 6;           // 64 float4 per row (D=256)
        int c4 = e4 & 63;
        int k  = g_idx[n];
        float4 q  = reinterpret_cast<const float4*>(cb + (size_t)k * D)[c4];
        float4 zv = reinterpret_cast<float4*>(out)[e4];
        float4 r;
        r.x = zv.x + (q.x - zv.x);
        r.y = zv.y + (q.y - zv.y);
        r.z = zv.z + (q.z - zv.z);
        r.w = zv.w + (q.w - zv.w);
        reinterpret_cast<float4*>(out)[e4] = r;
        float dx = zv.x - q.x, dy = zv.y - q.y, dz = zv.z - q.z, dw = zv.w - q.w;
        s += dx * dx + dy * dy + dz * dz + dw * dw;
    }
    __shared__ float sr[256];
    sr[threadIdx.x] = s;
    __syncthreads();
    for (int st = 128; st > 0; st >>= 1) {
        if (threadIdx.x < st) sr[threadIdx.x] += sr[threadIdx.x + st];
        __syncthreads();
    }
    if (threadIdx.x == 0) g_part[blockIdx.x] = sr[0];
}

// ---------------------------------------------------------------------------
// Kernel 5: finalize losses (deterministic tree reduce of 512 partials)
// ---------------------------------------------------------------------------
__global__ void finalize_kernel(float* __restrict__ out, int out_size,
                                float inv_count) {
    __shared__ float sr[512];
    int t = threadIdx.x;
    sr[t] = g_part[t];
    __syncthreads();
    for (int st = 256; st > 0; st >>= 1) {
        if (t < st) sr[t] += sr[t + st];
        __syncthreads();
    }
    if (t == 0) {
        float m = sr[0] * inv_count;
        out[out_size - 2] = m;   // dictionary_loss
        out[out_size - 1] = m;   // commitment_loss (identical forward value)
    }
}

// ---------------------------------------------------------------------------
extern "C" void kernel_launch(void* const* d_in, const int* in_sizes, int n_in,
                              void* d_out, int out_size) {
    const float* x  = (const float*)d_in[0];   // [M, 256]
    const float* W  = (const float*)d_in[1];   // [256, 256]
    const float* b  = (const float*)d_in[2];   // [256]
    const float* cb = (const float*)d_in[3];   // [Kcodes, 256]

    int M      = in_sizes[0] / D;              // 32768
    int Kcodes = in_sizes[3] / D;              // 8192
    float* out = (float*)d_out;                // x_recon lives in first M*D slots

    // 1. codebook norms
    cnorm_kernel<<<(Kcodes + 255) / 256, 256>>>(cb, Kcodes);

    // 2. projection z = x W^T + b  -> written into out (reused as z buffer)
    dim3 pg(M / BM, D / BN);
    proj_kernel<<<pg, NTHREADS>>>(x, W, b, out);

    // 3. argmin over codebook
    dist_argmin_kernel<<<M / BM, NTHREADS>>>(out, cb, Kcodes);

    // 4. gather + straight-through recon + loss partials (512 blocks fixed)
    int total4 = (M * D) / 4;
    gather_loss_kernel<<<512, 256>>>(out, cb, total4);

    // 5. finalize scalars
    finalize_kernel<<<1, 512>>>(out, out_size, 1.0f / (float)(M * D));
}

// round 3
// speedup vs baseline: 2.0368x; 2.0368x over previous
#include <cuda_runtime.h>
#include <cuda_bf16.h>
#include <math_constants.h>
#include <cstdint>

// ============================================================================
// Problem constants
// ============================================================================
#define D        256
#define MROWS    32768
#define KCODES   8192
#define NTILE    64            // KCODES / 128
#define BM       128
#define BN       128
#define BK       16
#define TM       8
#define TN       8
#define NTHREADS 256
#define APAD     24            // smem row stride in bf16 (48 B, ldmatrix conflict-free)

// ============================================================================
// Device scratch (no cudaMalloc allowed)
// ============================================================================
__device__ float          g_cn[KCODES];
__device__ int            g_idx[MROWS];
__device__ float          g_part[512];
__device__ __nv_bfloat16  g_cbh[KCODES * D];
__device__ __nv_bfloat16  g_cbl[KCODES * D];
__device__ __nv_bfloat16  g_zh[MROWS * D];
__device__ __nv_bfloat16  g_zl[MROWS * D];
__device__ float2         g_cv[(size_t)MROWS * NTILE];
__device__ int2           g_ci[(size_t)MROWS * NTILE];

// ============================================================================
// Helpers
// ============================================================================
__device__ __forceinline__ uint32_t smem_to_u32(const void* p) {
    uint32_t a;
    asm("{ .reg .u64 t; cvta.to.shared.u64 t, %1; cvt.u32.u64 %0, t; }"
        : "=r"(a) : "l"(p));
    return a;
}
__device__ __forceinline__ void cp16(uint32_t dst, const void* src) {
    asm volatile("cp.async.cg.shared.global [%0], [%1], 16;"
        :: "r"(dst), "l"(__cvta_generic_to_global(src)) : "memory");
}
__device__ __forceinline__ void ldsm_x4(uint32_t& r0, uint32_t& r1,
                                        uint32_t& r2, uint32_t& r3, uint32_t addr) {
    asm volatile("ldmatrix.sync.aligned.m8n8.x4.shared.b16 {%0,%1,%2,%3}, [%4];"
        : "=r"(r0), "=r"(r1), "=r"(r2), "=r"(r3) : "r"(addr));
}
__device__ __forceinline__ void mma16816(float* c, uint32_t a0, uint32_t a1,
                                         uint32_t a2, uint32_t a3,
                                         uint32_t b0, uint32_t b1) {
    asm volatile("mma.sync.aligned.m16n8k16.row.col.f32.bf16.bf16.f32 "
        "{%0,%1,%2,%3}, {%4,%5,%6,%7}, {%8,%9}, {%0,%1,%2,%3};"
        : "+f"(c[0]), "+f"(c[1]), "+f"(c[2]), "+f"(c[3])
        : "r"(a0), "r"(a1), "r"(a2), "r"(a3), "r"(b0), "r"(b1));
}
// merge top-2 pair (w0<=w1) into running top-2 (v0<=v1)
__device__ __forceinline__ void top2_merge(float& v0, int& i0, float& v1, int& i1,
                                           float w0, int j0, float w1, int j1) {
    if (w0 < v0) {
        if (v0 < w1) { v1 = v0; i1 = i0; } else { v1 = w1; i1 = j1; }
        v0 = w0; i0 = j0;
    } else if (w0 < v1) { v1 = w0; i1 = j0; }
}

// ============================================================================
// Kernel 1: codebook norms (exact fp32)
// ============================================================================
__global__ void cnorm_kernel(const float* __restrict__ cb, int Kcodes) {
    int k = blockIdx.x * blockDim.x + threadIdx.x;
    if (k >= Kcodes) return;
    const float4* row = reinterpret_cast<const float4*>(cb + (size_t)k * D);
    float s = 0.f;
#pragma unroll 8
    for (int i = 0; i < D / 4; ++i) {
        float4 v = row[i];
        s += v.x * v.x + v.y * v.y + v.z * v.z + v.w * v.w;
    }
    g_cn[k] = s;
}

// ============================================================================
// Kernel 2: split codebook into bf16 hi/lo
// ============================================================================
__global__ void split_cb_kernel(const float* __restrict__ cb, int total4) {
    int t = blockIdx.x * blockDim.x + threadIdx.x;
    if (t >= total4) return;
    float4 v = reinterpret_cast<const float4*>(cb)[t];
    __nv_bfloat16 h0 = __float2bfloat16(v.x), h1 = __float2bfloat16(v.y);
    __nv_bfloat16 h2 = __float2bfloat16(v.z), h3 = __float2bfloat16(v.w);
    __nv_bfloat162* ph = reinterpret_cast<__nv_bfloat162*>(g_cbh);
    __nv_bfloat162* pl = reinterpret_cast<__nv_bfloat162*>(g_cbl);
    ph[t * 2 + 0] = __nv_bfloat162(h0, h1);
    ph[t * 2 + 1] = __nv_bfloat162(h2, h3);
    pl[t * 2 + 0] = __nv_bfloat162(__float2bfloat16(v.x - __bfloat162float(h0)),
                                   __float2bfloat16(v.y - __bfloat162float(h1)));
    pl[t * 2 + 1] = __nv_bfloat162(__float2bfloat16(v.z - __bfloat162float(h2)),
                                   __float2bfloat16(v.w - __bfloat162float(h3)));
}

// ============================================================================
// Kernel 3: projection z = x W^T + b (fp32 SIMT) + bf16 hi/lo split of z
// ============================================================================
__device__ __forceinline__ void load_tile(float dst[BK][BM + 4],
                                          const float* __restrict__ src,
                                          int rowBase, int kt, int tid) {
#pragma unroll
    for (int p = 0; p < 2; ++p) {
        int id = tid + p * NTHREADS;
        int r = id >> 2, c4 = id & 3;
        float4 v = *reinterpret_cast<const float4*>(
            src + (size_t)(rowBase + r) * D + kt * BK + c4 * 4);
        dst[c4 * 4 + 0][r] = v.x;
        dst[c4 * 4 + 1][r] = v.y;
        dst[c4 * 4 + 2][r] = v.z;
        dst[c4 * 4 + 3][r] = v.w;
    }
}

__global__ __launch_bounds__(NTHREADS, 2)
void proj_kernel(const float* __restrict__ x, const float* __restrict__ W,
                 const float* __restrict__ b, float* __restrict__ z) {
    __shared__ float Xs[BK][BM + 4];
    __shared__ float Ws[BK][BN + 4];

    int tid = threadIdx.x;
    int tx = tid & 15, ty = tid >> 4;
    int rowBase = blockIdx.x * BM;
    int colBase = blockIdx.y * BN;

    float acc[TM][TN];
#pragma unroll
    for (int i = 0; i < TM; ++i)
#pragma unroll
        for (int j = 0; j < TN; ++j) acc[i][j] = 0.f;

    for (int kt = 0; kt < D / BK; ++kt) {
        load_tile(Xs, x, rowBase, kt, tid);
        load_tile(Ws, W, colBase, kt, tid);
        __syncthreads();
#pragma unroll
        for (int kk = 0; kk < BK; ++kk) {
            float a[TM], bb[TN];
#pragma unroll
            for (int i = 0; i < TM; ++i) a[i] = Xs[kk][ty * TM + i];
#pragma unroll
            for (int j = 0; j < TN; ++j) bb[j] = Ws[kk][tx * TN + j];
#pragma unroll
            for (int i = 0; i < TM; ++i)
#pragma unroll
                for (int j = 0; j < TN; ++j)
                    acc[i][j] = fmaf(a[i], bb[j], acc[i][j]);
        }
        __syncthreads();
    }

    int col0 = colBase + tx * TN;
#pragma unroll
    for (int i = 0; i < TM; ++i) {
        int row = rowBase + ty * TM + i;
        float* zrow = z + (size_t)row * D + col0;
        __nv_bfloat162* hrow = reinterpret_cast<__nv_bfloat162*>(g_zh + (size_t)row * D) + (col0 >> 1);
        __nv_bfloat162* lrow = reinterpret_cast<__nv_bfloat162*>(g_zl + (size_t)row * D) + (col0 >> 1);
#pragma unroll
        for (int j4 = 0; j4 < TN / 4; ++j4) {
            float4 v;
            v.x = acc[i][j4 * 4 + 0] + b[col0 + j4 * 4 + 0];
            v.y = acc[i][j4 * 4 + 1] + b[col0 + j4 * 4 + 1];
            v.z = acc[i][j4 * 4 + 2] + b[col0 + j4 * 4 + 2];
            v.w = acc[i][j4 * 4 + 3] + b[col0 + j4 * 4 + 3];
            *reinterpret_cast<float4*>(zrow + j4 * 4) = v;
            __nv_bfloat16 h0 = __float2bfloat16(v.x), h1 = __float2bfloat16(v.y);
            __nv_bfloat16 h2 = __float2bfloat16(v.z), h3 = __float2bfloat16(v.w);
            hrow[j4 * 2 + 0] = __nv_bfloat162(h0, h1);
            hrow[j4 * 2 + 1] = __nv_bfloat162(h2, h3);
            lrow[j4 * 2 + 0] = __nv_bfloat162(__float2bfloat16(v.x - __bfloat162float(h0)),
                                              __float2bfloat16(v.y - __bfloat162float(h1)));
            lrow[j4 * 2 + 1] = __nv_bfloat162(__float2bfloat16(v.z - __bfloat162float(h2)),
                                              __float2bfloat16(v.w - __bfloat162float(h3)));
        }
    }
}

// ============================================================================
// Kernel 4: distance GEMM on HMMA (mma.sync bf16), virtual K = 768:
//   A' = [z_hi | z_lo | z_hi], B' = [e_hi | e_hi | e_lo]
//   dot = zh.eh + zl.eh + zh.el ~= z.e (fp32-class accuracy for ordering)
// Each CTA: 128 rows x 128 codes, writes per-row top-2 candidates per n-tile.
// ============================================================================
__global__ __launch_bounds__(256, 2)
void dist_mma_kernel(int Kcodes) {
    __shared__ __align__(16) __nv_bfloat16 As[2][128 * APAD];
    __shared__ __align__(16) __nv_bfloat16 Bs[2][128 * APAD];
    __shared__ float4 red[128][4];

    const int tid = threadIdx.x, lane = tid & 31, wid = tid >> 5;
    const int wm = wid >> 2, wn = wid & 3;
    const int rowBase = blockIdx.x * 128;
    const int codeBase = blockIdx.y * 128;
    const int TB = 128 * APAD * 2;   // bytes per buffer

    // cp.async staging: thread -> (row, 16B-half)
    const int sr = tid >> 1, sh = tid & 1;
    const uint32_t asBase = smem_to_u32(As);
    const uint32_t bsBase = smem_to_u32(Bs);
    const uint32_t aDst = asBase + sr * (APAD * 2) + sh * 16;
    const uint32_t bDst = bsBase + sr * (APAD * 2) + sh * 16;

    // ldmatrix lane addressing
    const int q = lane >> 3, i8 = lane & 7;
    const uint32_t aLd = asBase + (((wm * 64) + (q & 1) * 8 + i8) * APAD + (q >> 1) * 8) * 2;
    const uint32_t bLd = bsBase + (((wn * 32) + (q >> 1) * 8 + i8) * APAD + (q & 1) * 8) * 2;

    float acc[4][4][4];
#pragma unroll
    for (int mt = 0; mt < 4; ++mt)
#pragma unroll
        for (int nt = 0; nt < 4; ++nt)
#pragma unroll
            for (int e = 0; e < 4; ++e) acc[mt][nt][e] = 0.f;

    // stage ktile 'kt' into buffer 'buf'
    auto stage = [&](int buf, int kt) {
        int seg = kt >> 4, kc = (kt & 15) << 4;
        const __nv_bfloat16* aS = (seg == 1) ? g_zl : g_zh;
        const __nv_bfloat16* bS = (seg == 2) ? g_cbl : g_cbh;
        cp16(aDst + buf * TB, aS + (size_t)(rowBase + sr) * D + kc + sh * 8);
        cp16(bDst + buf * TB, bS + (size_t)(codeBase + sr) * D + kc + sh * 8);
        asm volatile("cp.async.commit_group;" ::: "memory");
    };

    stage(0, 0);
    for (int kt = 0; kt < 48; ++kt) {
        int buf = kt & 1;
        if (kt < 47) {
            stage(buf ^ 1, kt + 1);
            asm volatile("cp.async.wait_group 1;" ::: "memory");
        } else {
            asm volatile("cp.async.wait_group 0;" ::: "memory");
        }
        __syncthreads();

        uint32_t a[4][4], bf[4][2];
#pragma unroll
        for (int mt = 0; mt < 4; ++mt)
            ldsm_x4(a[mt][0], a[mt][1], a[mt][2], a[mt][3],
                    aLd + buf * TB + mt * 16 * APAD * 2);
#pragma unroll
        for (int nt2 = 0; nt2 < 2; ++nt2) {
            uint32_t r0, r1, r2, r3;
            ldsm_x4(r0, r1, r2, r3, bLd + buf * TB + nt2 * 16 * APAD * 2);
            bf[nt2 * 2 + 0][0] = r0; bf[nt2 * 2 + 0][1] = r1;
            bf[nt2 * 2 + 1][0] = r2; bf[nt2 * 2 + 1][1] = r3;
        }
#pragma unroll
        for (int mt = 0; mt < 4; ++mt)
#pragma unroll
            for (int nt = 0; nt < 4; ++nt)
                mma16816(acc[mt][nt], a[mt][0], a[mt][1], a[mt][2], a[mt][3],
                         bf[nt][0], bf[nt][1]);
        __syncthreads();
    }

    // ---- epilogue: d = cn - 2*dot, per-row top-2 over this CTA's 128 codes ----
    const int g = lane >> 2;
    const int cb0 = codeBase + wn * 32 + (lane & 3) * 2;
    float cn8[4][2];
#pragma unroll
    for (int nt = 0; nt < 4; ++nt) {
        cn8[nt][0] = __ldg(&g_cn[cb0 + nt * 8 + 0]);
        cn8[nt][1] = __ldg(&g_cn[cb0 + nt * 8 + 1]);
    }
#pragma unroll
    for (int mt = 0; mt < 4; ++mt)
#pragma unroll
        for (int h = 0; h < 2; ++h) {
            float v0 = CUDART_INF_F, v1 = CUDART_INF_F;
            int i0 = 0, i1 = 0;
#pragma unroll
            for (int nt = 0; nt < 4; ++nt)
#pragma unroll
                for (int e = 0; e < 2; ++e) {
                    float dd = fmaf(-2.f, acc[mt][nt][h * 2 + e], cn8[nt][e]);
                    int code = cb0 + nt * 8 + e;
                    if (dd < v0) { v1 = v0; i1 = i0; v0 = dd; i0 = code; }
                    else if (dd < v1) { v1 = dd; i1 = code; }
                }
#pragma unroll
            for (int off = 1; off <= 2; off <<= 1) {
                float w0 = __shfl_xor_sync(0xffffffffu, v0, off);
                float w1 = __shfl_xor_sync(0xffffffffu, v1, off);
                int j0 = __shfl_xor_sync(0xffffffffu, i0, off);
                int j1 = __shfl_xor_sync(0xffffffffu, i1, off);
                top2_merge(v0, i0, v1, i1, w0, j0, w1, j1);
            }
            if ((lane & 3) == 0)
                red[wm * 64 + mt * 16 + h * 8 + g][wn] =
                    make_float4(v0, __int_as_float(i0), v1, __int_as_float(i1));
        }
    __syncthreads();

    if (tid < 128) {
        float v0 = CUDART_INF_F, v1 = CUDART_INF_F;
        int i0 = 0, i1 = 0;
#pragma unroll
        for (int w = 0; w < 4; ++w) {
            float4 p = red[tid][w];
            top2_merge(v0, i0, v1, i1, p.x, __float_as_int(p.y), p.z, __float_as_int(p.w));
        }
        size_t slot = (size_t)(rowBase + tid) * gridDim.y + blockIdx.y;
        g_cv[slot] = make_float2(v0, v1);
        g_ci[slot] = make_int2(i0, i1);
    }
}

// ============================================================================
// Kernel 5: per-row reduce (approx top-4 of 2*NT candidates) + exact fp32
// rescore with d = cn - 2*z.e (same formula as the passing fp32 round).
// One warp per row.
// ============================================================================
__global__ __launch_bounds__(256)
void reduce_rescore_kernel(const float* __restrict__ z,
                           const float* __restrict__ cb, int NT) {
    int row = blockIdx.x * 8 + (threadIdx.x >> 5);
    int lane = threadIdx.x & 31;

    float v[4];
    int ix[4];
#pragma unroll
    for (int k = 0; k < 4; ++k) { v[k] = CUDART_INF_F; ix[k] = -1; }
#pragma unroll
    for (int p = 0; p < 2; ++p) {
        int s = lane + p * 32;
        if (s < NT) {
            float2 cv = g_cv[(size_t)row * NT + s];
            int2 ci = g_ci[(size_t)row * NT + s];
            v[p * 2 + 0] = cv.x; ix[p * 2 + 0] = ci.x;
            v[p * 2 + 1] = cv.y; ix[p * 2 + 1] = ci.y;
        }
    }

    // pass 1: global approx top-2
    float a0 = CUDART_INF_F, a1 = CUDART_INF_F; int b0 = -1, b1 = -1;
#pragma unroll
    for (int k = 0; k < 4; ++k) {
        if (v[k] < a0) { a1 = a0; b1 = b0; a0 = v[k]; b0 = ix[k]; }
        else if (v[k] < a1) { a1 = v[k]; b1 = ix[k]; }
    }
#pragma unroll
    for (int off = 16; off > 0; off >>= 1) {
        float w0 = __shfl_xor_sync(0xffffffffu, a0, off);
        float w1 = __shfl_xor_sync(0xffffffffu, a1, off);
        int j0 = __shfl_xor_sync(0xffffffffu, b0, off);
        int j1 = __shfl_xor_sync(0xffffffffu, b1, off);
        top2_merge(a0, b0, a1, b1, w0, j0, w1, j1);
    }
    int t0 = b0, t1 = b1;

    // pass 2: approx ranks 3-4 (exclude t0, t1)
    float c0 = CUDART_INF_F, c1 = CUDART_INF_F; int d0 = -1, d1 = -1;
#pragma unroll
    for (int k = 0; k < 4; ++k) {
        if (ix[k] != t0 && ix[k] != t1 && ix[k] >= 0) {
            if (v[k] < c0) { c1 = c0; d1 = d0; c0 = v[k]; d0 = ix[k]; }
            else if (v[k] < c1) { c1 = v[k]; d1 = ix[k]; }
        }
    }
#pragma unroll
    for (int off = 16; off > 0; off >>= 1) {
        float w0 = __shfl_xor_sync(0xffffffffu, c0, off);
        float w1 = __shfl_xor_sync(0xffffffffu, c1, off);
        int j0 = __shfl_xor_sync(0xffffffffu, d0, off);
        int j1 = __shfl_xor_sync(0xffffffffu, d1, off);
        top2_merge(c0, d0, c1, d1, w0, j0, w1, j1);
    }

    int jj[4] = { t0, t1, (d0 >= 0 ? d0 : t0), (d1 >= 0 ? d1 : t1) };

    // exact fp32 rescore: d_j = cn[j] - 2 * z.e_j
    const float4* zr = reinterpret_cast<const float4*>(z + (size_t)row * D);
    const float4* e0 = reinterpret_cast<const float4*>(cb + (size_t)jj[0] * D);
    const float4* e1 = reinterpret_cast<const float4*>(cb + (size_t)jj[1] * D);
    const float4* e2 = reinterpret_cast<const float4*>(cb + (size_t)jj[2] * D);
    const float4* e3 = reinterpret_cast<const float4*>(cb + (size_t)jj[3] * D);
    float s0 = 0.f, s1 = 0.f, s2 = 0.f, s3 = 0.f;
#pragma unroll
    for (int p = 0; p < 2; ++p) {
        int qd = lane + p * 32;
        float4 zv = zr[qd];
        float4 a = e0[qd];
        s0 = fmaf(zv.x, a.x, s0); s0 = fmaf(zv.y, a.y, s0);
        s0 = fmaf(zv.z, a.z, s0); s0 = fmaf(zv.w, a.w, s0);
        a = e1[qd];
        s1 = fmaf(zv.x, a.x, s1); s1 = fmaf(zv.y, a.y, s1);
        s1 = fmaf(zv.z, a.z, s1); s1 = fmaf(zv.w, a.w, s1);
        a = e2[qd];
        s2 = fmaf(zv.x, a.x, s2); s2 = fmaf(zv.y, a.y, s2);
        s2 = fmaf(zv.z, a.z, s2); s2 = fmaf(zv.w, a.w, s2);
        a = e3[qd];
        s3 = fmaf(zv.x, a.x, s3); s3 = fmaf(zv.y, a.y, s3);
        s3 = fmaf(zv.z, a.z, s3); s3 = fmaf(zv.w, a.w, s3);
    }
#pragma unroll
    for (int off = 16; off > 0; off >>= 1) {
        s0 += __shfl_xor_sync(0xffffffffu, s0, off);
        s1 += __shfl_xor_sync(0xffffffffu, s1, off);
        s2 += __shfl_xor_sync(0xffffffffu, s2, off);
        s3 += __shfl_xor_sync(0xffffffffu, s3, off);
    }
    if (lane == 0) {
        float dj[4];
        dj[0] = g_cn[jj[0]] - 2.f * s0;
        dj[1] = g_cn[jj[1]] - 2.f * s1;
        dj[2] = g_cn[jj[2]] - 2.f * s2;
        dj[3] = g_cn[jj[3]] - 2.f * s3;
        float best = dj[0]; int bi = jj[0];
#pragma unroll
        for (int k = 1; k < 4; ++k)
            if (dj[k] < best || (dj[k] == best && jj[k] < bi)) { best = dj[k]; bi = jj[k]; }
        g_idx[row] = bi;
    }
}

// ============================================================================
// Kernel 6: gather + straight-through recon + loss partials
// ============================================================================
__global__ void gather_loss_kernel(float* __restrict__ out,
                                   const float* __restrict__ cb,
                                   int total4) {
    int t = blockIdx.x * blockDim.x + threadIdx.x;
    int stride = gridDim.x * blockDim.x;
    float s = 0.f;
    for (int e4 = t; e4 < total4; e4 += stride) {
        int n = e4 >> 6;
        int c4 = e4 & 63;
        int k = g_idx[n];
        float4 qv = reinterpret_cast<const float4*>(cb + (size_t)k * D)[c4];
        float4 zv = reinterpret_cast<float4*>(out)[e4];
        reinterpret_cast<float4*>(out)[e4] = qv;   // z + (q - z) == q
        float dx = zv.x - qv.x, dy = zv.y - qv.y, dz = zv.z - qv.z, dw = zv.w - qv.w;
        s += dx * dx + dy * dy + dz * dz + dw * dw;
    }
    __shared__ float sr[256];
    sr[threadIdx.x] = s;
    __syncthreads();
    for (int st = 128; st > 0; st >>= 1) {
        if (threadIdx.x < st) sr[threadIdx.x] += sr[threadIdx.x + st];
        __syncthreads();
    }
    if (threadIdx.x == 0) g_part[blockIdx.x] = sr[0];
}

// ============================================================================
// Kernel 7: finalize losses
// ============================================================================
__global__ void finalize_kernel(float* __restrict__ out, int out_size,
                                float inv_count) {
    __shared__ float sr[512];
    int t = threadIdx.x;
    sr[t] = g_part[t];
    __syncthreads();
    for (int st = 256; st > 0; st >>= 1) {
        if (t < st) sr[t] += sr[t + st];
        __syncthreads();
    }
    if (t == 0) {
        float m = sr[0] * inv_count;
        out[out_size - 2] = m;
        out[out_size - 1] = m;
    }
}

// ============================================================================
extern "C" void kernel_launch(void* const* d_in, const int* in_sizes, int n_in,
                              void* d_out, int out_size) {
    const float* x  = (const float*)d_in[0];
    const float* W  = (const float*)d_in[1];
    const float* b  = (const float*)d_in[2];
    const float* cb = (const float*)d_in[3];

    int M      = in_sizes[0] / D;   // 32768
    int Kcodes = in_sizes[3] / D;   // 8192
    int NT     = Kcodes / 128;      // 64
    float* out = (float*)d_out;

    // 1. codebook norms + bf16 hi/lo split
    cnorm_kernel<<<(Kcodes + 255) / 256, 256>>>(cb, Kcodes);
    split_cb_kernel<<<(Kcodes * D / 4 + 255) / 256, 256>>>(cb, Kcodes * D / 4);

    // 2. projection (fp32 z into out, plus bf16 hi/lo of z)
    dim3 pg(M / BM, D / BN);
    proj_kernel<<<pg, NTHREADS>>>(x, W, b, out);

    // 3. HMMA distance GEMM, per-tile top-2 candidates
    dist_mma_kernel<<<dim3(M / 128, NT), 256>>>(Kcodes);

    // 4. reduce candidates + exact fp32 rescore of top-4
    reduce_rescore_kernel<<<M / 8, 256>>>(out, cb, NT);

    // 5. gather + losses
    gather_loss_kernel<<<512, 256>>>(out, cb, (M * D) / 4);

    // 6. finalize
    finalize_kernel<<<1, 512>>>(out, out_size, 1.0f / (float)(M * D));
}

// round 4
// speedup vs baseline: 3.3252x; 1.6325x over previous
#include <cuda_runtime.h>
#include <cuda_bf16.h>
#include <math_constants.h>
#include <cstdint>

// ============================================================================
// Problem constants
// ============================================================================
#define D        256
#define MROWS    32768
#define KCODES   8192
#define NTILE    64            // KCODES / 128
#define BM       128
#define BN       128
#define BK       16
#define TM       8
#define TN       8
#define NTHREADS 256
#define APAD     24            // smem row stride in bf16 (48 B, ldmatrix conflict-free)

// ============================================================================
// Device scratch (no cudaMalloc allowed)
// ============================================================================
__device__ float          g_cn[KCODES];
__device__ int            g_idx[MROWS];
__device__ float          g_part[512];
__device__ __nv_bfloat16  g_cbh[KCODES * D];
__device__ __nv_bfloat16  g_zh[MROWS * D];
__device__ __nv_bfloat16  g_zl[MROWS * D];
__device__ float2         g_cv[(size_t)MROWS * NTILE];
__device__ int2           g_ci[(size_t)MROWS * NTILE];

// ============================================================================
// Helpers
// ============================================================================
__device__ __forceinline__ uint32_t smem_to_u32(const void* p) {
    uint32_t a;
    asm("{ .reg .u64 t; cvta.to.shared.u64 t, %1; cvt.u32.u64 %0, t; }"
        : "=r"(a) : "l"(p));
    return a;
}
__device__ __forceinline__ void cp16(uint32_t dst, const void* src) {
    asm volatile("cp.async.cg.shared.global [%0], [%1], 16;"
        :: "r"(dst), "l"(__cvta_generic_to_global(src)) : "memory");
}
__device__ __forceinline__ void ldsm_x4(uint32_t& r0, uint32_t& r1,
                                        uint32_t& r2, uint32_t& r3, uint32_t addr) {
    asm volatile("ldmatrix.sync.aligned.m8n8.x4.shared.b16 {%0,%1,%2,%3}, [%4];"
        : "=r"(r0), "=r"(r1), "=r"(r2), "=r"(r3) : "r"(addr));
}
__device__ __forceinline__ void mma16816(float* c, uint32_t a0, uint32_t a1,
                                         uint32_t a2, uint32_t a3,
                                         uint32_t b0, uint32_t b1) {
    asm volatile("mma.sync.aligned.m16n8k16.row.col.f32.bf16.bf16.f32 "
        "{%0,%1,%2,%3}, {%4,%5,%6,%7}, {%8,%9}, {%0,%1,%2,%3};"
        : "+f"(c[0]), "+f"(c[1]), "+f"(c[2]), "+f"(c[3])
        : "r"(a0), "r"(a1), "r"(a2), "r"(a3), "r"(b0), "r"(b1));
}
__device__ __forceinline__ void top2_merge(float& v0, int& i0, float& v1, int& i1,
                                           float w0, int j0, float w1, int j1) {
    if (w0 < v0) {
        if (v0 < w1) { v1 = v0; i1 = i0; } else { v1 = w1; i1 = j1; }
        v0 = w0; i0 = j0;
    } else if (w0 < v1) { v1 = w0; i1 = j0; }
}

// ============================================================================
// Kernel 1: fused codebook norms + bf16 hi-split (one pass over cb)
// One warp per codebook row.
// ============================================================================
__global__ __launch_bounds__(256)
void cnsplit_kernel(const float* __restrict__ cb) {
    int row = blockIdx.x * 8 + (threadIdx.x >> 5);
    int lane = threadIdx.x & 31;
    const float4* src = reinterpret_cast<const float4*>(cb + (size_t)row * D);
    __nv_bfloat162* dh = reinterpret_cast<__nv_bfloat162*>(g_cbh + (size_t)row * D);
    float s = 0.f;
#pragma unroll
    for (int p = 0; p < 2; ++p) {
        int q = lane + p * 32;
        float4 v = src[q];
        s += v.x * v.x + v.y * v.y + v.z * v.z + v.w * v.w;
        dh[q * 2 + 0] = __nv_bfloat162(__float2bfloat16(v.x), __float2bfloat16(v.y));
        dh[q * 2 + 1] = __nv_bfloat162(__float2bfloat16(v.z), __float2bfloat16(v.w));
    }
#pragma unroll
    for (int o = 16; o > 0; o >>= 1) s += __shfl_xor_sync(0xffffffffu, s, o);
    if (lane == 0) g_cn[row] = s;
}

// ============================================================================
// Kernel 2: projection z = x W^T + b (fp32 SIMT) + bf16 hi/lo split of z
// ============================================================================
__device__ __forceinline__ void load_tile(float dst[BK][BM + 4],
                                          const float* __restrict__ src,
                                          int rowBase, int kt, int tid) {
#pragma unroll
    for (int p = 0; p < 2; ++p) {
        int id = tid + p * NTHREADS;
        int r = id >> 2, c4 = id & 3;
        float4 v = *reinterpret_cast<const float4*>(
            src + (size_t)(rowBase + r) * D + kt * BK + c4 * 4);
        dst[c4 * 4 + 0][r] = v.x;
        dst[c4 * 4 + 1][r] = v.y;
        dst[c4 * 4 + 2][r] = v.z;
        dst[c4 * 4 + 3][r] = v.w;
    }
}

__global__ __launch_bounds__(NTHREADS, 2)
void proj_kernel(const float* __restrict__ x, const float* __restrict__ W,
                 const float* __restrict__ b, float* __restrict__ z) {
    __shared__ float Xs[BK][BM + 4];
    __shared__ float Ws[BK][BN + 4];

    int tid = threadIdx.x;
    int tx = tid & 15, ty = tid >> 4;
    int rowBase = blockIdx.x * BM;
    int colBase = blockIdx.y * BN;

    float acc[TM][TN];
#pragma unroll
    for (int i = 0; i < TM; ++i)
#pragma unroll
        for (int j = 0; j < TN; ++j) acc[i][j] = 0.f;

    for (int kt = 0; kt < D / BK; ++kt) {
        load_tile(Xs, x, rowBase, kt, tid);
        load_tile(Ws, W, colBase, kt, tid);
        __syncthreads();
#pragma unroll
        for (int kk = 0; kk < BK; ++kk) {
            float a[TM], bb[TN];
#pragma unroll
            for (int i = 0; i < TM; ++i) a[i] = Xs[kk][ty * TM + i];
#pragma unroll
            for (int j = 0; j < TN; ++j) bb[j] = Ws[kk][tx * TN + j];
#pragma unroll
            for (int i = 0; i < TM; ++i)
#pragma unroll
                for (int j = 0; j < TN; ++j)
                    acc[i][j] = fmaf(a[i], bb[j], acc[i][j]);
        }
        __syncthreads();
    }

    int col0 = colBase + tx * TN;
#pragma unroll
    for (int i = 0; i < TM; ++i) {
        int row = rowBase + ty * TM + i;
        float* zrow = z + (size_t)row * D + col0;
        __nv_bfloat162* hrow = reinterpret_cast<__nv_bfloat162*>(g_zh + (size_t)row * D) + (col0 >> 1);
        __nv_bfloat162* lrow = reinterpret_cast<__nv_bfloat162*>(g_zl + (size_t)row * D) + (col0 >> 1);
#pragma unroll
        for (int j4 = 0; j4 < TN / 4; ++j4) {
            float4 v;
            v.x = acc[i][j4 * 4 + 0] + b[col0 + j4 * 4 + 0];
            v.y = acc[i][j4 * 4 + 1] + b[col0 + j4 * 4 + 1];
            v.z = acc[i][j4 * 4 + 2] + b[col0 + j4 * 4 + 2];
            v.w = acc[i][j4 * 4 + 3] + b[col0 + j4 * 4 + 3];
            *reinterpret_cast<float4*>(zrow + j4 * 4) = v;
            __nv_bfloat16 h0 = __float2bfloat16(v.x), h1 = __float2bfloat16(v.y);
            __nv_bfloat16 h2 = __float2bfloat16(v.z), h3 = __float2bfloat16(v.w);
            hrow[j4 * 2 + 0] = __nv_bfloat162(h0, h1);
            hrow[j4 * 2 + 1] = __nv_bfloat162(h2, h3);
            lrow[j4 * 2 + 0] = __nv_bfloat162(__float2bfloat16(v.x - __bfloat162float(h0)),
                                              __float2bfloat16(v.y - __bfloat162float(h1)));
            lrow[j4 * 2 + 1] = __nv_bfloat162(__float2bfloat16(v.z - __bfloat162float(h2)),
                                              __float2bfloat16(v.w - __bfloat162float(h3)));
        }
    }
}

// ============================================================================
// Kernel 3: distance GEMM on HMMA, 2-term split:
//   dot = zh.eh + zl.eh = z.eh      (z.el error absorbed by exact rescore)
// Per k-chunk (16), e_hi is loaded ONCE and MMA'd against both zh and zl.
// 16 iterations, 1 barrier each, cp.async 1-stage-ahead prefetch.
// CTA = 128 rows x 128 codes; per-row top-2 per tile -> candidates.
// ============================================================================
__global__ __launch_bounds__(256, 2)
void dist_mma_kernel(int Kcodes) {
    // stage = {zh tile, zl tile, eh tile}, each 128 x 16 bf16 (APAD-padded)
    __shared__ __align__(16) __nv_bfloat16 Sm[2][3][128 * APAD];
    __shared__ float4 red[128][4];

    const int tid = threadIdx.x, lane = tid & 31, wid = tid >> 5;
    const int wm = wid >> 2, wn = wid & 3;
    const int rowBase = blockIdx.x * 128;
    const int codeBase = blockIdx.y * 128;
    const int TILEB = 128 * APAD * 2;        // bytes per tile
    const int STAGEB = 3 * TILEB;            // bytes per stage

    const int sr = tid >> 1, sh = tid & 1;   // staging: row, 16B-half
    const uint32_t smBase = smem_to_u32(Sm);
    const uint32_t stDst = smBase + sr * (APAD * 2) + sh * 16;

    // ldmatrix lane addressing (within a tile)
    const int q = lane >> 3, i8 = lane & 7;
    const uint32_t aOff = (uint32_t)(((wm * 64) + (q & 1) * 8 + i8) * APAD + (q >> 1) * 8) * 2;
    const uint32_t bOff = (uint32_t)(((wn * 32) + (q >> 1) * 8 + i8) * APAD + (q & 1) * 8) * 2;

    float acc[4][4][4];
#pragma unroll
    for (int mt = 0; mt < 4; ++mt)
#pragma unroll
        for (int nt = 0; nt < 4; ++nt)
#pragma unroll
            for (int e = 0; e < 4; ++e) acc[mt][nt][e] = 0.f;

    auto stage = [&](int buf, int kt) {
        int kc = kt << 4;
        uint32_t base = stDst + buf * STAGEB;
        cp16(base,              g_zh  + (size_t)(rowBase  + sr) * D + kc + sh * 8);
        cp16(base + TILEB,      g_zl  + (size_t)(rowBase  + sr) * D + kc + sh * 8);
        cp16(base + 2 * TILEB,  g_cbh + (size_t)(codeBase + sr) * D + kc + sh * 8);
        asm volatile("cp.async.commit_group;" ::: "memory");
    };

    stage(0, 0);
    for (int kt = 0; kt < 16; ++kt) {
        int buf = kt & 1;
        asm volatile("cp.async.wait_group 0;" ::: "memory");
        __syncthreads();
        // prefetch next chunk into the other buffer (all warps past barrier,
        // so the other buffer's previous contents are fully consumed)
        if (kt < 15) stage(buf ^ 1, kt + 1);

        uint32_t tbase = smBase + buf * STAGEB;
        uint32_t ah[4][4], al[4][4], bf[4][2];
#pragma unroll
        for (int mt = 0; mt < 4; ++mt) {
            ldsm_x4(ah[mt][0], ah[mt][1], ah[mt][2], ah[mt][3],
                    tbase + aOff + (uint32_t)(mt * 16 * APAD * 2));
            ldsm_x4(al[mt][0], al[mt][1], al[mt][2], al[mt][3],
                    tbase + TILEB + aOff + (uint32_t)(mt * 16 * APAD * 2));
        }
#pragma unroll
        for (int nt2 = 0; nt2 < 2; ++nt2) {
            uint32_t r0, r1, r2, r3;
            ldsm_x4(r0, r1, r2, r3,
                    tbase + 2 * TILEB + bOff + (uint32_t)(nt2 * 16 * APAD * 2));
            bf[nt2 * 2 + 0][0] = r0; bf[nt2 * 2 + 0][1] = r1;
            bf[nt2 * 2 + 1][0] = r2; bf[nt2 * 2 + 1][1] = r3;
        }
#pragma unroll
        for (int mt = 0; mt < 4; ++mt)
#pragma unroll
            for (int nt = 0; nt < 4; ++nt) {
                mma16816(acc[mt][nt], ah[mt][0], ah[mt][1], ah[mt][2], ah[mt][3],
                         bf[nt][0], bf[nt][1]);
                mma16816(acc[mt][nt], al[mt][0], al[mt][1], al[mt][2], al[mt][3],
                         bf[nt][0], bf[nt][1]);
            }
    }

    // ---- epilogue: d = cn - 2*dot, per-row top-2 over this CTA's 128 codes ----
    const int g = lane >> 2;
    const int cb0 = codeBase + wn * 32 + (lane & 3) * 2;
    float cn8[4][2];
#pragma unroll
    for (int nt = 0; nt < 4; ++nt) {
        cn8[nt][0] = __ldg(&g_cn[cb0 + nt * 8 + 0]);
        cn8[nt][1] = __ldg(&g_cn[cb0 + nt * 8 + 1]);
    }
#pragma unroll
    for (int mt = 0; mt < 4; ++mt)
#pragma unroll
        for (int h = 0; h < 2; ++h) {
            float v0 = CUDART_INF_F, v1 = CUDART_INF_F;
            int i0 = 0, i1 = 0;
#pragma unroll
            for (int nt = 0; nt < 4; ++nt)
#pragma unroll
                for (int e = 0; e < 2; ++e) {
                    float dd = fmaf(-2.f, acc[mt][nt][h * 2 + e], cn8[nt][e]);
                    int code = cb0 + nt * 8 + e;
                    if (dd < v0) { v1 = v0; i1 = i0; v0 = dd; i0 = code; }
                    else if (dd < v1) { v1 = dd; i1 = code; }
                }
#pragma unroll
            for (int off = 1; off <= 2; off <<= 1) {
                float w0 = __shfl_xor_sync(0xffffffffu, v0, off);
                float w1 = __shfl_xor_sync(0xffffffffu, v1, off);
                int j0 = __shfl_xor_sync(0xffffffffu, i0, off);
                int j1 = __shfl_xor_sync(0xffffffffu, i1, off);
                top2_merge(v0, i0, v1, i1, w0, j0, w1, j1);
            }
            if ((lane & 3) == 0)
                red[wm * 64 + mt * 16 + h * 8 + g][wn] =
                    make_float4(v0, __int_as_float(i0), v1, __int_as_float(i1));
        }
    __syncthreads();

    if (tid < 128) {
        float v0 = CUDART_INF_F, v1 = CUDART_INF_F;
        int i0 = 0, i1 = 0;
#pragma unroll
        for (int w = 0; w < 4; ++w) {
            float4 p = red[tid][w];
            top2_merge(v0, i0, v1, i1, p.x, __float_as_int(p.y), p.z, __float_as_int(p.w));
        }
        size_t slot = (size_t)(rowBase + tid) * gridDim.y + blockIdx.y;
        g_cv[slot] = make_float2(v0, v1);
        g_ci[slot] = make_int2(i0, i1);
    }
}

// ============================================================================
// Kernel 4: per-row reduce (approx top-4 of 2*NT candidates) + exact fp32
// rescore with d = cn - 2*z.e. One warp per row.
// ============================================================================
__global__ __launch_bounds__(256)
void reduce_rescore_kernel(const float* __restrict__ z,
                           const float* __restrict__ cb, int NT) {
    int row = blockIdx.x * 8 + (threadIdx.x >> 5);
    int lane = threadIdx.x & 31;

    float v[4];
    int ix[4];
#pragma unroll
    for (int k = 0; k < 4; ++k) { v[k] = CUDART_INF_F; ix[k] = -1; }
#pragma unroll
    for (int p = 0; p < 2; ++p) {
        int s = lane + p * 32;
        if (s < NT) {
            float2 cv = g_cv[(size_t)row * NT + s];
            int2 ci = g_ci[(size_t)row * NT + s];
            v[p * 2 + 0] = cv.x; ix[p * 2 + 0] = ci.x;
            v[p * 2 + 1] = cv.y; ix[p * 2 + 1] = ci.y;
        }
    }

    float a0 = CUDART_INF_F, a1 = CUDART_INF_F; int b0 = -1, b1 = -1;
#pragma unroll
    for (int k = 0; k < 4; ++k) {
        if (v[k] < a0) { a1 = a0; b1 = b0; a0 = v[k]; b0 = ix[k]; }
        else if (v[k] < a1) { a1 = v[k]; b1 = ix[k]; }
    }
#pragma unroll
    for (int off = 16; off > 0; off >>= 1) {
        float w0 = __shfl_xor_sync(0xffffffffu, a0, off);
        float w1 = __shfl_xor_sync(0xffffffffu, a1, off);
        int j0 = __shfl_xor_sync(0xffffffffu, b0, off);
        int j1 = __shfl_xor_sync(0xffffffffu, b1, off);
        top2_merge(a0, b0, a1, b1, w0, j0, w1, j1);
    }
    int t0 = b0, t1 = b1;

    float c0 = CUDART_INF_F, c1 = CUDART_INF_F; int d0 = -1, d1 = -1;
#pragma unroll
    for (int k = 0; k < 4; ++k) {
        if (ix[k] != t0 && ix[k] != t1 && ix[k] >= 0) {
            if (v[k] < c0) { c1 = c0; d1 = d0; c0 = v[k]; d0 = ix[k]; }
            else if (v[k] < c1) { c1 = v[k]; d1 = ix[k]; }
        }
    }
#pragma unroll
    for (int off = 16; off > 0; off >>= 1) {
        float w0 = __shfl_xor_sync(0xffffffffu, c0, off);
        float w1 = __shfl_xor_sync(0xffffffffu, c1, off);
        int j0 = __shfl_xor_sync(0xffffffffu, d0, off);
        int j1 = __shfl_xor_sync(0xffffffffu, d1, off);
        top2_merge(c0, d0, c1, d1, w0, j0, w1, j1);
    }

    int jj[4] = { t0, t1, (d0 >= 0 ? d0 : t0), (d1 >= 0 ? d1 : t1) };

    const float4* zr = reinterpret_cast<const float4*>(z + (size_t)row * D);
    const float4* e0 = reinterpret_cast<const float4*>(cb + (size_t)jj[0] * D);
    const float4* e1 = reinterpret_cast<const float4*>(cb + (size_t)jj[1] * D);
    const float4* e2 = reinterpret_cast<const float4*>(cb + (size_t)jj[2] * D);
    const float4* e3 = reinterpret_cast<const float4*>(cb + (size_t)jj[3] * D);
    float s0 = 0.f, s1 = 0.f, s2 = 0.f, s3 = 0.f;
#pragma unroll
    for (int p = 0; p < 2; ++p) {
        int qd = lane + p * 32;
        float4 zv = zr[qd];
        float4 a = e0[qd];
        s0 = fmaf(zv.x, a.x, s0); s0 = fmaf(zv.y, a.y, s0);
        s0 = fmaf(zv.z, a.z, s0); s0 = fmaf(zv.w, a.w, s0);
        a = e1[qd];
        s1 = fmaf(zv.x, a.x, s1); s1 = fmaf(zv.y, a.y, s1);
        s1 = fmaf(zv.z, a.z, s1); s1 = fmaf(zv.w, a.w, s1);
        a = e2[qd];
        s2 = fmaf(zv.x, a.x, s2); s2 = fmaf(zv.y, a.y, s2);
        s2 = fmaf(zv.z, a.z, s2); s2 = fmaf(zv.w, a.w, s2);
        a = e3[qd];
        s3 = fmaf(zv.x, a.x, s3); s3 = fmaf(zv.y, a.y, s3);
        s3 = fmaf(zv.z, a.z, s3); s3 = fmaf(zv.w, a.w, s3);
    }
#pragma unroll
    for (int off = 16; off > 0; off >>= 1) {
        s0 += __shfl_xor_sync(0xffffffffu, s0, off);
        s1 += __shfl_xor_sync(0xffffffffu, s1, off);
        s2 += __shfl_xor_sync(0xffffffffu, s2, off);
        s3 += __shfl_xor_sync(0xffffffffu, s3, off);
    }
    if (lane == 0) {
        float dj[4];
        dj[0] = g_cn[jj[0]] - 2.f * s0;
        dj[1] = g_cn[jj[1]] - 2.f * s1;
        dj[2] = g_cn[jj[2]] - 2.f * s2;
        dj[3] = g_cn[jj[3]] - 2.f * s3;
        float best = dj[0]; int bi = jj[0];
#pragma unroll
        for (int k = 1; k < 4; ++k)
            if (dj[k] < best || (dj[k] == best && jj[k] < bi)) { best = dj[k]; bi = jj[k]; }
        g_idx[row] = bi;
    }
}

// ============================================================================
// Kernel 5: gather + straight-through recon + loss partials
// ============================================================================
__global__ void gather_loss_kernel(float* __restrict__ out,
                                   const float* __restrict__ cb,
                                   int total4) {
    int t = blockIdx.x * blockDim.x + threadIdx.x;
    int stride = gridDim.x * blockDim.x;
    float s = 0.f;
    for (int e4 = t; e4 < total4; e4 += stride) {
        int n = e4 >> 6;
        int c4 = e4 & 63;
        int k = g_idx[n];
        float4 qv = reinterpret_cast<const float4*>(cb + (size_t)k * D)[c4];
        float4 zv = reinterpret_cast<float4*>(out)[e4];
        reinterpret_cast<float4*>(out)[e4] = qv;   // z + (q - z) == q
        float dx = zv.x - qv.x, dy = zv.y - qv.y, dz = zv.z - qv.z, dw = zv.w - qv.w;
        s += dx * dx + dy * dy + dz * dz + dw * dw;
    }
    __shared__ float sr[256];
    sr[threadIdx.x] = s;
    __syncthreads();
    for (int st = 128; st > 0; st >>= 1) {
        if (threadIdx.x < st) sr[threadIdx.x] += sr[threadIdx.x + st];
        __syncthreads();
    }
    if (threadIdx.x == 0) g_part[blockIdx.x] = sr[0];
}

// ============================================================================
// Kernel 6: finalize losses
// ============================================================================
__global__ void finalize_kernel(float* __restrict__ out, int out_size,
                                float inv_count) {
    __shared__ float sr[512];
    int t = threadIdx.x;
    sr[t] = g_part[t];
    __syncthreads();
    for (int st = 256; st > 0; st >>= 1) {
        if (t < st) sr[t] += sr[t + st];
        __syncthreads();
    }
    if (t == 0) {
        float m = sr[0] * inv_count;
        out[out_size - 2] = m;
        out[out_size - 1] = m;
    }
}

// ============================================================================
extern "C" void kernel_launch(void* const* d_in, const int* in_sizes, int n_in,
                              void* d_out, int out_size) {
    const float* x  = (const float*)d_in[0];
    const float* W  = (const float*)d_in[1];
    const float* b  = (const float*)d_in[2];
    const float* cb = (const float*)d_in[3];

    int M      = in_sizes[0] / D;   // 32768
    int Kcodes = in_sizes[3] / D;   // 8192
    int NT     = Kcodes / 128;      // 64
    float* out = (float*)d_out;

    // 1. fused codebook norms + bf16 hi split
    cnsplit_kernel<<<Kcodes / 8, 256>>>(cb);

    // 2. projection (fp32 z into out, plus bf16 hi/lo of z)
    dim3 pg(M / BM, D / BN);
    proj_kernel<<<pg, NTHREADS>>>(x, W, b, out);

    // 3. HMMA distance GEMM (2-term), per-tile top-2 candidates
    dist_mma_kernel<<<dim3(M / 128, NT), 256>>>(Kcodes);

    // 4. reduce candidates + exact fp32 rescore of top-4
    reduce_rescore_kernel<<<M / 8, 256>>>(out, cb, NT);

    // 5. gather + losses
    gather_loss_kernel<<<512, 256>>>(out, cb, (M * D) / 4);

    // 6. finalize
    finalize_kernel<<<1, 512>>>(out, out_size, 1.0f / (float)(M * D));
}